// round 1
// baseline (speedup 1.0000x reference)
#include <cuda_runtime.h>
#include <math_constants.h>

// Problem constants
#define LQ   15876          // L = 126*126 patches
#define HO   126
#define D    27
#define DP   28             // padded dim (float4 friendly), pad value = 0
#define SPLIT 8             // split-K over keys
#define BQ   256            // queries per CTA (1 per thread)
#define BK   128            // key tile in smem
#define NQB  ((LQ + BQ - 1) / BQ)          // 63
#define CH   ((LQ + SPLIT - 1) / SPLIT)    // 1985 keys per chunk

// Scratch (no allocations allowed -> device globals)
__device__ __align__(16) float g_K[LQ * DP];          // x patches (keys/values)
__device__ __align__(16) float g_Q[LQ * DP];          // y patches (queries)
__device__ float g_yyc[LQ];                            // ||X_m||^2 * log2e/0.35
__device__ float g_pm[SPLIT * LQ];                     // partial max (log2 domain)
__device__ float g_ps[SPLIT * LQ];                     // partial sum
__device__ __align__(16) float g_pacc[SPLIT * LQ * DP];
__device__ __align__(16) float g_outP[LQ * DP];        // attention output patches

__device__ __forceinline__ float ex2(float x) {
    float r;
    asm("ex2.approx.ftz.f32 %0, %1;" : "=f"(r) : "f"(x));
    return r;
}

// ---------------------------------------------------------------------------
// Kernel A: patch extraction + key squared norms
// ---------------------------------------------------------------------------
__global__ void extract_kernel(const float* __restrict__ x,
                               const float* __restrict__ y) {
    int m = blockIdx.x * blockDim.x + threadIdx.x;
    if (m >= LQ) return;
    int ph = m / HO, pw = m % HO;
    const float YSC = 1.4426950408889634f / 0.35f;   // log2e / (h^2 + 0.1)
    float yy = 0.f;
#pragma unroll
    for (int c = 0; c < 3; c++)
#pragma unroll
        for (int ki = 0; ki < 3; ki++)
#pragma unroll
            for (int kj = 0; kj < 3; kj++) {
                int j = c * 9 + ki * 3 + kj;
                float vx = x[c * 16384 + (ph + ki) * 128 + (pw + kj)];
                float vy = y[c * 16384 + (ph + ki) * 128 + (pw + kj)];
                g_K[m * DP + j] = vx;
                g_Q[m * DP + j] = vy;
                yy = fmaf(vx, vx, yy);
            }
    g_K[m * DP + 27] = 0.f;
    g_Q[m * DP + 27] = 0.f;
    g_yyc[m] = yy * YSC;
}

// ---------------------------------------------------------------------------
// Kernel B: flash attention, split-K. One query per thread, keys tiled in smem.
// scores computed in log2 domain: sc = dot * (2*log2e/0.35) - yyc[m]
// (the -||R_l||^2 row constant cancels in softmax and is dropped)
// ---------------------------------------------------------------------------
__global__ __launch_bounds__(BQ, 2) void attn_kernel() {
    __shared__ __align__(16) float sK[BK * DP];
    __shared__ float sY[BK];

    int tid = threadIdx.x;
    int q = blockIdx.x * BQ + tid;
    int ql = q < LQ ? q : LQ - 1;
    int k0 = blockIdx.y * CH;
    int k1 = min(k0 + CH, LQ);

    const float S2 = 2.0f * 1.4426950408889634f / 0.35f;

    float qv[DP];
#pragma unroll
    for (int j = 0; j < DP; j += 4) {
        float4 t = *(const float4*)&g_Q[ql * DP + j];
        qv[j] = t.x; qv[j + 1] = t.y; qv[j + 2] = t.z; qv[j + 3] = t.w;
    }
    float acc[DP];
#pragma unroll
    for (int j = 0; j < DP; j++) acc[j] = 0.f;
    float mmax = -CUDART_INF_F;
    float ssum = 0.f;

    for (int kt = k0; kt < k1; kt += BK) {
        int nk = min(BK, k1 - kt);
        // cooperative tile load (float4)
        for (int t = tid; t < nk * (DP / 4); t += BQ) {
            int kr = t / (DP / 4), p = t % (DP / 4);
            ((float4*)sK)[kr * (DP / 4) + p] =
                ((const float4*)g_K)[(kt + kr) * (DP / 4) + p];
        }
        for (int t = tid; t < nk; t += BQ) sY[t] = g_yyc[kt + t];
        __syncthreads();

#pragma unroll 2
        for (int kk = 0; kk < nk; kk++) {
            const float4* krow = (const float4*)&sK[kk * DP];
            float kv[DP];
#pragma unroll
            for (int p = 0; p < DP / 4; p++) {
                float4 t = krow[p];
                kv[4 * p] = t.x; kv[4 * p + 1] = t.y;
                kv[4 * p + 2] = t.z; kv[4 * p + 3] = t.w;
            }
            float d0 = 0.f, d1 = 0.f, d2 = 0.f, d3 = 0.f;
#pragma unroll
            for (int j = 0; j < DP; j += 4) {
                d0 = fmaf(qv[j], kv[j], d0);
                d1 = fmaf(qv[j + 1], kv[j + 1], d1);
                d2 = fmaf(qv[j + 2], kv[j + 2], d2);
                d3 = fmaf(qv[j + 3], kv[j + 3], d3);
            }
            float sc = fmaf((d0 + d1) + (d2 + d3), S2, -sY[kk]);
            if (sc > mmax) {            // rare rescale (peaked softmax)
                float corr = ex2(mmax - sc);
                ssum *= corr;
#pragma unroll
                for (int j = 0; j < DP; j++) acc[j] *= corr;
                mmax = sc;
            }
            float p = ex2(sc - mmax);
            ssum += p;
#pragma unroll
            for (int j = 0; j < DP; j++) acc[j] = fmaf(p, kv[j], acc[j]);
        }
        __syncthreads();
    }

    if (q < LQ) {
        int sidx = blockIdx.y * LQ + q;
        g_pm[sidx] = mmax;
        g_ps[sidx] = ssum;
        float4* dst = (float4*)&g_pacc[(size_t)sidx * DP];
#pragma unroll
        for (int p = 0; p < DP / 4; p++) {
            float4 t;
            t.x = acc[4 * p]; t.y = acc[4 * p + 1];
            t.z = acc[4 * p + 2]; t.w = acc[4 * p + 3];
            dst[p] = t;
        }
    }
}

// ---------------------------------------------------------------------------
// Kernel C: log-sum-exp merge of the SPLIT partials, normalize, write patches
// ---------------------------------------------------------------------------
__global__ void merge_kernel() {
    int q = blockIdx.x * blockDim.x + threadIdx.x;
    if (q >= LQ) return;
    float M = -CUDART_INF_F;
#pragma unroll
    for (int s = 0; s < SPLIT; s++) M = fmaxf(M, g_pm[s * LQ + q]);
    float tot = 0.f;
    float o[DP];
#pragma unroll
    for (int j = 0; j < DP; j++) o[j] = 0.f;
#pragma unroll
    for (int s = 0; s < SPLIT; s++) {
        float w = ex2(g_pm[s * LQ + q] - M);
        tot = fmaf(g_ps[s * LQ + q], w, tot);
        const float4* src = (const float4*)&g_pacc[(size_t)(s * LQ + q) * DP];
#pragma unroll
        for (int p = 0; p < DP / 4; p++) {
            float4 t = src[p];
            o[4 * p]     = fmaf(t.x, w, o[4 * p]);
            o[4 * p + 1] = fmaf(t.y, w, o[4 * p + 1]);
            o[4 * p + 2] = fmaf(t.z, w, o[4 * p + 2]);
            o[4 * p + 3] = fmaf(t.w, w, o[4 * p + 3]);
        }
    }
    float inv = 1.0f / tot;
#pragma unroll
    for (int p = 0; p < DP / 4; p++) {
        float4 t;
        t.x = o[4 * p] * inv; t.y = o[4 * p + 1] * inv;
        t.z = o[4 * p + 2] * inv; t.w = o[4 * p + 3] * inv;
        ((float4*)&g_outP[q * DP])[p] = t;
    }
}

// ---------------------------------------------------------------------------
// Kernel D: overlap-add fold with analytic contribution counts
// ---------------------------------------------------------------------------
__global__ void fold_kernel(float* __restrict__ out) {
    int idx = blockIdx.x * blockDim.x + threadIdx.x;
    if (idx >= 3 * 128 * 128) return;
    int c = idx / 16384;
    int h = (idx / 128) % 128;
    int w = idx % 128;
    int nh = min(h, 125) - max(0, h - 2) + 1;
    int nw = min(w, 125) - max(0, w - 2) + 1;
    float sum = 0.f;
#pragma unroll
    for (int ki = 0; ki < 3; ki++) {
        int ph = h - ki;
        if (ph < 0 || ph >= HO) continue;
#pragma unroll
        for (int kj = 0; kj < 3; kj++) {
            int pw = w - kj;
            if (pw < 0 || pw >= HO) continue;
            sum += g_outP[(ph * HO + pw) * DP + c * 9 + ki * 3 + kj];
        }
    }
    out[idx] = sum / (float)(nh * nw);
}

// ---------------------------------------------------------------------------
extern "C" void kernel_launch(void* const* d_in, const int* in_sizes, int n_in,
                              void* d_out, int out_size) {
    const float* x = (const float*)d_in[0];
    const float* y = (const float*)d_in[1];
    float* out = (float*)d_out;

    extract_kernel<<<(LQ + 255) / 256, 256>>>(x, y);
    dim3 grid(NQB, SPLIT);
    attn_kernel<<<grid, BQ>>>();
    merge_kernel<<<(LQ + 255) / 256, 256>>>();
    fold_kernel<<<(3 * 128 * 128 + 255) / 256, 256>>>(out);
}

// round 3
// speedup vs baseline: 1.0789x; 1.0789x over previous
#include <cuda_runtime.h>
#include <math_constants.h>

// Problem constants
#define LQ   15876          // L = 126*126 patches
#define HO   126
#define D    27
#define DP   28             // padded dim (float4/f32x2 friendly), pad = 0
#define SPLIT 9             // split-K over keys (15876 = 9 * 1764 exactly)
#define BQ   256            // queries per CTA (1 per thread)
#define BK   128            // key tile in smem
#define NQB  ((LQ + BQ - 1) / BQ)          // 63
#define CH   (LQ / SPLIT)                  // 1764 keys per chunk (NOT BK-mult!)
#define DP2  (DP / 2)                      // 14 packed f32x2 values

typedef unsigned long long u64;

// Scratch (no allocations allowed -> device globals)
__device__ __align__(16) float g_K[LQ * DP];          // x patches (keys/values)
__device__ __align__(16) float g_Q[LQ * DP];          // y patches (queries)
__device__ float g_yyc[LQ];                            // ||X_m||^2 * log2e/0.35
__device__ float g_pm[SPLIT * LQ];                     // partial max (log2 dom)
__device__ float g_ps[SPLIT * LQ];                     // partial sum
__device__ __align__(16) float g_pacc[SPLIT * LQ * DP];
__device__ __align__(16) float g_outP[LQ * DP];        // attention out patches

__device__ __forceinline__ float ex2(float x) {
    float r;
    asm("ex2.approx.ftz.f32 %0, %1;" : "=f"(r) : "f"(x));
    return r;
}
__device__ __forceinline__ u64 pack2(float a, float b) {
    u64 r;
    asm("mov.b64 %0, {%1, %2};" : "=l"(r) : "f"(a), "f"(b));
    return r;
}
__device__ __forceinline__ void unpack2(u64 v, float& a, float& b) {
    asm("mov.b64 {%0, %1}, %2;" : "=f"(a), "=f"(b) : "l"(v));
}
// d = a*b + d  (packed 2x fp32)
__device__ __forceinline__ void fma2(u64& d, u64 a, u64 b) {
    asm("fma.rn.f32x2 %0, %1, %2, %0;" : "+l"(d) : "l"(a), "l"(b));
}
__device__ __forceinline__ void add2(u64& d, u64 a) {
    asm("add.rn.f32x2 %0, %0, %1;" : "+l"(d) : "l"(a));
}
__device__ __forceinline__ void mul2(u64& d, u64 a) {
    asm("mul.rn.f32x2 %0, %0, %1;" : "+l"(d) : "l"(a));
}

// ---------------------------------------------------------------------------
// Kernel A: patch extraction + key squared norms
// ---------------------------------------------------------------------------
__global__ void extract_kernel(const float* __restrict__ x,
                               const float* __restrict__ y) {
    int m = blockIdx.x * blockDim.x + threadIdx.x;
    if (m >= LQ) return;
    int ph = m / HO, pw = m % HO;
    const float YSC = 1.4426950408889634f / 0.35f;   // log2e / (h^2 + 0.1)
    float yy = 0.f;
#pragma unroll
    for (int c = 0; c < 3; c++)
#pragma unroll
        for (int ki = 0; ki < 3; ki++)
#pragma unroll
            for (int kj = 0; kj < 3; kj++) {
                int j = c * 9 + ki * 3 + kj;
                float vx = x[c * 16384 + (ph + ki) * 128 + (pw + kj)];
                float vy = y[c * 16384 + (ph + ki) * 128 + (pw + kj)];
                g_K[m * DP + j] = vx;
                g_Q[m * DP + j] = vy;
                yy = fmaf(vx, vx, yy);
            }
    g_K[m * DP + 27] = 0.f;
    g_Q[m * DP + 27] = 0.f;
    g_yyc[m] = yy * YSC;
}

// ---------------------------------------------------------------------------
// Kernel B: flash attention, split-K, packed f32x2 math.
// score (log2 domain): sc = dot * (2*log2e/0.35) - yyc[m]
// ---------------------------------------------------------------------------
__global__ __launch_bounds__(BQ, 2) void attn_kernel() {
    __shared__ __align__(16) float sK[BK * DP];
    __shared__ float sY[BK];

    int tid = threadIdx.x;
    int q = blockIdx.x * BQ + tid;
    int ql = q < LQ ? q : LQ - 1;
    int k0 = blockIdx.y * CH;
    int k1 = k0 + CH;

    const float S2 = 2.0f * 1.4426950408889634f / 0.35f;

    u64 qv[DP2];
#pragma unroll
    for (int p = 0; p < DP2 / 2; p++) {
        ulonglong2 t = ((const ulonglong2*)&g_Q[ql * DP])[p];
        qv[2 * p] = t.x; qv[2 * p + 1] = t.y;
    }
    u64 acc[DP2];
#pragma unroll
    for (int j = 0; j < DP2; j++) acc[j] = 0ull;
    float mmax = -CUDART_INF_F;
    float ssum = 0.f;

    for (int kt = k0; kt < k1; kt += BK) {
        int nk = min(BK, k1 - kt);          // CH is not a BK multiple!
        // cooperative tile load (float4)
        for (int t = tid; t < nk * (DP / 4); t += BQ) {
            int kr = t / (DP / 4), p = t % (DP / 4);
            ((float4*)sK)[kr * (DP / 4) + p] =
                ((const float4*)g_K)[(kt + kr) * (DP / 4) + p];
        }
        for (int t = tid; t < nk; t += BQ) sY[t] = g_yyc[kt + t];
        __syncthreads();

        for (int kk = 0; kk < nk; kk++) {
            const ulonglong2* krow = (const ulonglong2*)&sK[kk * DP];
            u64 kv[DP2];
#pragma unroll
            for (int p = 0; p < DP2 / 2; p++) {
                ulonglong2 t = krow[p];
                kv[2 * p] = t.x; kv[2 * p + 1] = t.y;
            }
            // packed dot product, 4 accumulators for ILP
            u64 d0 = 0ull, d1 = 0ull, d2 = 0ull, d3 = 0ull;
#pragma unroll
            for (int j = 0; j < 12; j += 4) {
                fma2(d0, qv[j], kv[j]);
                fma2(d1, qv[j + 1], kv[j + 1]);
                fma2(d2, qv[j + 2], kv[j + 2]);
                fma2(d3, qv[j + 3], kv[j + 3]);
            }
            fma2(d0, qv[12], kv[12]);
            fma2(d1, qv[13], kv[13]);
            add2(d0, d1); add2(d2, d3); add2(d0, d2);
            float lo, hi;
            unpack2(d0, lo, hi);
            float sc = fmaf(lo + hi, S2, -sY[kk]);

            if (sc > mmax) {            // rare rescale (peaked softmax)
                float corr = ex2(mmax - sc);
                u64 c2 = pack2(corr, corr);
                ssum *= corr;
#pragma unroll
                for (int j = 0; j < DP2; j++) mul2(acc[j], c2);
                mmax = sc;
            }
            float p = ex2(sc - mmax);
            ssum += p;
            u64 p2 = pack2(p, p);
#pragma unroll
            for (int j = 0; j < DP2; j++) fma2(acc[j], p2, kv[j]);
        }
        __syncthreads();
    }

    if (q < LQ) {
        int sidx = blockIdx.y * LQ + q;
        g_pm[sidx] = mmax;
        g_ps[sidx] = ssum;
        ulonglong2* dst = (ulonglong2*)&g_pacc[(size_t)sidx * DP];
#pragma unroll
        for (int p = 0; p < DP2 / 2; p++) {
            ulonglong2 t;
            t.x = acc[2 * p]; t.y = acc[2 * p + 1];
            dst[p] = t;
        }
    }
}

// ---------------------------------------------------------------------------
// Kernel C: log-sum-exp merge of the SPLIT partials, normalize
// ---------------------------------------------------------------------------
__global__ void merge_kernel() {
    int q = blockIdx.x * blockDim.x + threadIdx.x;
    if (q >= LQ) return;
    float M = -CUDART_INF_F;
#pragma unroll
    for (int s = 0; s < SPLIT; s++) M = fmaxf(M, g_pm[s * LQ + q]);
    float tot = 0.f;
    float o[DP];
#pragma unroll
    for (int j = 0; j < DP; j++) o[j] = 0.f;
#pragma unroll
    for (int s = 0; s < SPLIT; s++) {
        float w = ex2(g_pm[s * LQ + q] - M);
        tot = fmaf(g_ps[s * LQ + q], w, tot);
        const float4* src = (const float4*)&g_pacc[(size_t)(s * LQ + q) * DP];
#pragma unroll
        for (int p = 0; p < DP / 4; p++) {
            float4 t = src[p];
            o[4 * p]     = fmaf(t.x, w, o[4 * p]);
            o[4 * p + 1] = fmaf(t.y, w, o[4 * p + 1]);
            o[4 * p + 2] = fmaf(t.z, w, o[4 * p + 2]);
            o[4 * p + 3] = fmaf(t.w, w, o[4 * p + 3]);
        }
    }
    float inv = 1.0f / tot;
#pragma unroll
    for (int p = 0; p < DP / 4; p++) {
        float4 t;
        t.x = o[4 * p] * inv; t.y = o[4 * p + 1] * inv;
        t.z = o[4 * p + 2] * inv; t.w = o[4 * p + 3] * inv;
        ((float4*)&g_outP[q * DP])[p] = t;
    }
}

// ---------------------------------------------------------------------------
// Kernel D: overlap-add fold with analytic contribution counts
// ---------------------------------------------------------------------------
__global__ void fold_kernel(float* __restrict__ out) {
    int idx = blockIdx.x * blockDim.x + threadIdx.x;
    if (idx >= 3 * 128 * 128) return;
    int c = idx / 16384;
    int h = (idx / 128) % 128;
    int w = idx % 128;
    int nh = min(h, 125) - max(0, h - 2) + 1;
    int nw = min(w, 125) - max(0, w - 2) + 1;
    float sum = 0.f;
#pragma unroll
    for (int ki = 0; ki < 3; ki++) {
        int ph = h - ki;
        if (ph < 0 || ph >= HO) continue;
#pragma unroll
        for (int kj = 0; kj < 3; kj++) {
            int pw = w - kj;
            if (pw < 0 || pw >= HO) continue;
            sum += g_outP[(ph * HO + pw) * DP + c * 9 + ki * 3 + kj];
        }
    }
    out[idx] = sum / (float)(nh * nw);
}

// ---------------------------------------------------------------------------
extern "C" void kernel_launch(void* const* d_in, const int* in_sizes, int n_in,
                              void* d_out, int out_size) {
    const float* x = (const float*)d_in[0];
    const float* y = (const float*)d_in[1];
    float* out = (float*)d_out;

    extract_kernel<<<(LQ + 255) / 256, 256>>>(x, y);
    dim3 grid(NQB, SPLIT);
    attn_kernel<<<grid, BQ>>>();
    merge_kernel<<<(LQ + 255) / 256, 256>>>();
    fold_kernel<<<(3 * 128 * 128 + 255) / 256, 256>>>(out);
}

// round 4
// speedup vs baseline: 1.1802x; 1.0939x over previous
#include <cuda_runtime.h>
#include <math_constants.h>

// Problem constants
#define LQ   15876          // L = 126*126 patches
#define HO   126
#define D    27
#define DP   28             // padded dim; K pad = 1.0 (ssum trick), Q pad = 0
#define SPLIT 14            // split-K over keys (15876 = 14 * 1134)
#define BQ   256            // queries per CTA (1 per thread)
#define BK   128            // key tile in smem
#define NQB  ((LQ + BQ - 1) / BQ)          // 63
#define CH   (LQ / SPLIT)                  // 1134 keys per chunk (not BK-mult)
#define DP2  (DP / 2)                      // 14 packed f32x2 values

typedef unsigned long long u64;

// Scratch (no allocations allowed -> device globals)
__device__ __align__(16) float g_K[LQ * DP];          // x patches (keys/vals)
__device__ __align__(16) float g_Q[LQ * DP];          // y patches (queries)
__device__ float g_yyc[LQ];                            // ||X_m||^2 * log2e/0.35
__device__ float g_pm[SPLIT * LQ];                     // partial max (log2 dom)
__device__ __align__(16) float g_pacc[SPLIT * LQ * DP]; // [..27] holds ssum
__device__ __align__(16) float g_outP[LQ * DP];        // attention out patches

__device__ __forceinline__ float ex2(float x) {
    float r;
    asm("ex2.approx.ftz.f32 %0, %1;" : "=f"(r) : "f"(x));
    return r;
}
__device__ __forceinline__ u64 pack2(float a, float b) {
    u64 r;
    asm("mov.b64 %0, {%1, %2};" : "=l"(r) : "f"(a), "f"(b));
    return r;
}
__device__ __forceinline__ void unpack2(u64 v, float& a, float& b) {
    asm("mov.b64 {%0, %1}, %2;" : "=f"(a), "=f"(b) : "l"(v));
}
// d = a*b + c  (packed 2x fp32), explicit 4-operand form
__device__ __forceinline__ u64 fma2v(u64 a, u64 b, u64 c) {
    u64 d;
    asm("fma.rn.f32x2 %0, %1, %2, %3;" : "=l"(d) : "l"(a), "l"(b), "l"(c));
    return d;
}
__device__ __forceinline__ u64 add2v(u64 a, u64 b) {
    u64 d;
    asm("add.rn.f32x2 %0, %1, %2;" : "=l"(d) : "l"(a), "l"(b));
    return d;
}
__device__ __forceinline__ u64 mul2v(u64 a, u64 b) {
    u64 d;
    asm("mul.rn.f32x2 %0, %1, %2;" : "=l"(d) : "l"(a), "l"(b));
    return d;
}
// load two adjacent u64 (16B) from shared
__device__ __forceinline__ void lds_v2u64(u64& a, u64& b, const void* p) {
    asm("ld.shared.v2.b64 {%0, %1}, [%2];"
        : "=l"(a), "=l"(b) : "l"((size_t)__cvta_generic_to_shared(p)));
}

// ---------------------------------------------------------------------------
// Kernel A: patch extraction + key squared norms. K pad=1.0, Q pad=0.0
// ---------------------------------------------------------------------------
__global__ void extract_kernel(const float* __restrict__ x,
                               const float* __restrict__ y) {
    int m = blockIdx.x * blockDim.x + threadIdx.x;
    if (m >= LQ) return;
    int ph = m / HO, pw = m % HO;
    const float YSC = 1.4426950408889634f / 0.35f;   // log2e / (h^2 + 0.1)
    float yy = 0.f;
#pragma unroll
    for (int c = 0; c < 3; c++)
#pragma unroll
        for (int ki = 0; ki < 3; ki++)
#pragma unroll
            for (int kj = 0; kj < 3; kj++) {
                int j = c * 9 + ki * 3 + kj;
                float vx = x[c * 16384 + (ph + ki) * 128 + (pw + kj)];
                float vy = y[c * 16384 + (ph + ki) * 128 + (pw + kj)];
                g_K[m * DP + j] = vx;
                g_Q[m * DP + j] = vy;
                yy = fmaf(vx, vx, yy);
            }
    g_K[m * DP + 27] = 1.0f;     // ssum-in-accumulator trick
    g_Q[m * DP + 27] = 0.0f;     // keeps dot product exact
    g_yyc[m] = yy * YSC;
}

// ---------------------------------------------------------------------------
// Kernel B: flash attention, split-K, packed f32x2 math.
// score (log2 domain): sc = dot * (2*log2e/0.35) - yyc[m]
// acc[27] accumulates sum of softmax weights (K pad element = 1)
// ---------------------------------------------------------------------------
__global__ __launch_bounds__(BQ, 2) void attn_kernel() {
    __shared__ __align__(16) float sK[BK * DP];
    __shared__ float sY[BK];

    int tid = threadIdx.x;
    int q = blockIdx.x * BQ + tid;
    int ql = q < LQ ? q : LQ - 1;
    int k0 = blockIdx.y * CH;
    int k1 = k0 + CH;

    const float S2 = 2.0f * 1.4426950408889634f / 0.35f;

    u64 qv[DP2];
#pragma unroll
    for (int p = 0; p < DP2 / 2; p++) {
        ulonglong2 t = ((const ulonglong2*)&g_Q[ql * DP])[p];
        qv[2 * p] = t.x; qv[2 * p + 1] = t.y;
    }
    u64 acc[DP2];
#pragma unroll
    for (int j = 0; j < DP2; j++) acc[j] = 0ull;
    float mmax = -CUDART_INF_F;

    for (int kt = k0; kt < k1; kt += BK) {
        int nk = min(BK, k1 - kt);          // CH is not a BK multiple
        for (int t = tid; t < nk * (DP / 4); t += BQ) {
            int kr = t / (DP / 4), p = t % (DP / 4);
            ((float4*)sK)[kr * (DP / 4) + p] =
                ((const float4*)g_K)[(kt + kr) * (DP / 4) + p];
        }
        for (int t = tid; t < nk; t += BQ) sY[t] = g_yyc[kt + t];
        __syncthreads();

        for (int kk = 0; kk < nk; kk++) {
            const char* krow = (const char*)&sK[kk * DP];
            u64 kv[DP2];
#pragma unroll
            for (int p = 0; p < DP2 / 2; p++)
                lds_v2u64(kv[2 * p], kv[2 * p + 1], krow + 16 * p);

            // packed dot product, 2 chains
            u64 d0 = fma2v(qv[0], kv[0], 0ull);
            u64 d1 = fma2v(qv[1], kv[1], 0ull);
#pragma unroll
            for (int j = 2; j < DP2; j += 2) {
                d0 = fma2v(qv[j], kv[j], d0);
                d1 = fma2v(qv[j + 1], kv[j + 1], d1);
            }
            d0 = add2v(d0, d1);
            float lo, hi;
            unpack2(d0, lo, hi);
            float sc = fmaf(lo + hi, S2, -sY[kk]);

            if (sc > mmax) {            // rare rescale (peaked softmax)
                float corr = ex2(mmax - sc);
                u64 c2 = pack2(corr, corr);
#pragma unroll
                for (int j = 0; j < DP2; j++) acc[j] = mul2v(acc[j], c2);
                mmax = sc;
            }
            float p = ex2(sc - mmax);
            u64 p2 = pack2(p, p);
#pragma unroll
            for (int j = 0; j < DP2; j++) acc[j] = fma2v(p2, kv[j], acc[j]);
        }
        __syncthreads();
    }

    if (q < LQ) {
        int sidx = blockIdx.y * LQ + q;
        g_pm[sidx] = mmax;
        ulonglong2* dst = (ulonglong2*)&g_pacc[(size_t)sidx * DP];
#pragma unroll
        for (int p = 0; p < DP2 / 2; p++) {
            ulonglong2 t;
            t.x = acc[2 * p]; t.y = acc[2 * p + 1];
            dst[p] = t;
        }
    }
}

// ---------------------------------------------------------------------------
// Kernel C: log-sum-exp merge of the SPLIT partials, normalize.
// o[27] = total softmax mass (from the K-pad trick)
// ---------------------------------------------------------------------------
__global__ void merge_kernel() {
    int q = blockIdx.x * blockDim.x + threadIdx.x;
    if (q >= LQ) return;
    float M = -CUDART_INF_F;
#pragma unroll
    for (int s = 0; s < SPLIT; s++) M = fmaxf(M, g_pm[s * LQ + q]);
    float o[DP];
#pragma unroll
    for (int j = 0; j < DP; j++) o[j] = 0.f;
#pragma unroll
    for (int s = 0; s < SPLIT; s++) {
        float w = ex2(g_pm[s * LQ + q] - M);
        const float4* src = (const float4*)&g_pacc[(size_t)(s * LQ + q) * DP];
#pragma unroll
        for (int p = 0; p < DP / 4; p++) {
            float4 t = src[p];
            o[4 * p]     = fmaf(t.x, w, o[4 * p]);
            o[4 * p + 1] = fmaf(t.y, w, o[4 * p + 1]);
            o[4 * p + 2] = fmaf(t.z, w, o[4 * p + 2]);
            o[4 * p + 3] = fmaf(t.w, w, o[4 * p + 3]);
        }
    }
    float inv = 1.0f / o[27];
#pragma unroll
    for (int p = 0; p < DP / 4; p++) {
        float4 t;
        t.x = o[4 * p] * inv; t.y = o[4 * p + 1] * inv;
        t.z = o[4 * p + 2] * inv; t.w = o[4 * p + 3] * inv;
        ((float4*)&g_outP[q * DP])[p] = t;
    }
}

// ---------------------------------------------------------------------------
// Kernel D: overlap-add fold with analytic contribution counts
// ---------------------------------------------------------------------------
__global__ void fold_kernel(float* __restrict__ out) {
    int idx = blockIdx.x * blockDim.x + threadIdx.x;
    if (idx >= 3 * 128 * 128) return;
    int c = idx / 16384;
    int h = (idx / 128) % 128;
    int w = idx % 128;
    int nh = min(h, 125) - max(0, h - 2) + 1;
    int nw = min(w, 125) - max(0, w - 2) + 1;
    float sum = 0.f;
#pragma unroll
    for (int ki = 0; ki < 3; ki++) {
        int ph = h - ki;
        if (ph < 0 || ph >= HO) continue;
#pragma unroll
        for (int kj = 0; kj < 3; kj++) {
            int pw = w - kj;
            if (pw < 0 || pw >= HO) continue;
            sum += g_outP[(ph * HO + pw) * DP + c * 9 + ki * 3 + kj];
        }
    }
    out[idx] = sum / (float)(nh * nw);
}

// ---------------------------------------------------------------------------
extern "C" void kernel_launch(void* const* d_in, const int* in_sizes, int n_in,
                              void* d_out, int out_size) {
    const float* x = (const float*)d_in[0];
    const float* y = (const float*)d_in[1];
    float* out = (float*)d_out;

    extract_kernel<<<(LQ + 255) / 256, 256>>>(x, y);
    dim3 grid(NQB, SPLIT);
    attn_kernel<<<grid, BQ>>>();
    merge_kernel<<<(LQ + 255) / 256, 256>>>();
    fold_kernel<<<(3 * 128 * 128 + 255) / 256, 256>>>(out);
}

// round 6
// speedup vs baseline: 1.4004x; 1.1866x over previous
#include <cuda_runtime.h>
#include <math_constants.h>

// Problem constants
#define LQ   15876          // L = 126*126 patches
#define HO   126
#define D    27
#define DP   28             // padded dim; K pad = 1.0 (ssum trick), Q pad = 0
#define SPLIT 14            // split-K over keys (15876 = 14 * 1134)
#define BQ   256            // queries per CTA (1 per thread)
#define BK   128            // key tile in smem
#define NQB  ((LQ + BQ - 1) / BQ)          // 63
#define CH   (LQ / SPLIT)                  // 1134 keys per chunk (not BK-mult)
#define DP2  (DP / 2)                      // 14 packed f32x2 values
#define SKIP_THR 30.0f      // log2 skip threshold: dropped mass <= L*2^-30

typedef unsigned long long u64;

// Scratch (no allocations allowed -> device globals)
__device__ __align__(16) float g_K[LQ * DP];          // x patches (keys/vals)
__device__ __align__(16) float g_Q[LQ * DP];          // y patches (queries)
__device__ float g_yyc[LQ];                            // ||X_m||^2 * log2e/0.35
__device__ float g_pm[SPLIT * LQ];                     // partial max (log2 dom)
__device__ __align__(16) float g_pacc[SPLIT * LQ * DP]; // [..27] holds ssum
__device__ __align__(16) float g_outP[LQ * DP];        // attention out patches

__device__ __forceinline__ float ex2(float x) {
    float r;
    asm("ex2.approx.ftz.f32 %0, %1;" : "=f"(r) : "f"(x));
    return r;
}
__device__ __forceinline__ u64 pack2(float a, float b) {
    u64 r;
    asm("mov.b64 %0, {%1, %2};" : "=l"(r) : "f"(a), "f"(b));
    return r;
}
__device__ __forceinline__ void unpack2(u64 v, float& a, float& b) {
    asm("mov.b64 {%0, %1}, %2;" : "=f"(a), "=f"(b) : "l"(v));
}
// d = a*b + c  (packed 2x fp32)
__device__ __forceinline__ u64 fma2v(u64 a, u64 b, u64 c) {
    u64 d;
    asm("fma.rn.f32x2 %0, %1, %2, %3;" : "=l"(d) : "l"(a), "l"(b), "l"(c));
    return d;
}
__device__ __forceinline__ u64 add2v(u64 a, u64 b) {
    u64 d;
    asm("add.rn.f32x2 %0, %1, %2;" : "=l"(d) : "l"(a), "l"(b));
    return d;
}
__device__ __forceinline__ u64 mul2v(u64 a, u64 b) {
    u64 d;
    asm("mul.rn.f32x2 %0, %1, %2;" : "=l"(d) : "l"(a), "l"(b));
    return d;
}
// load two adjacent u64 (16B) from shared
__device__ __forceinline__ void lds_v2u64(u64& a, u64& b, const void* p) {
    asm("ld.shared.v2.b64 {%0, %1}, [%2];"
        : "=l"(a), "=l"(b) : "l"((size_t)__cvta_generic_to_shared(p)));
}

// ---------------------------------------------------------------------------
// Kernel A: patch extraction + key squared norms. K pad=1.0, Q pad=0.0
// ---------------------------------------------------------------------------
__global__ void extract_kernel(const float* __restrict__ x,
                               const float* __restrict__ y) {
    int m = blockIdx.x * blockDim.x + threadIdx.x;
    if (m >= LQ) return;
    int ph = m / HO, pw = m % HO;
    const float YSC = 1.4426950408889634f / 0.35f;   // log2e / (h^2 + 0.1)
    float yy = 0.f;
#pragma unroll
    for (int c = 0; c < 3; c++)
#pragma unroll
        for (int ki = 0; ki < 3; ki++)
#pragma unroll
            for (int kj = 0; kj < 3; kj++) {
                int j = c * 9 + ki * 3 + kj;
                float vx = x[c * 16384 + (ph + ki) * 128 + (pw + kj)];
                float vy = y[c * 16384 + (ph + ki) * 128 + (pw + kj)];
                g_K[m * DP + j] = vx;
                g_Q[m * DP + j] = vy;
                yy = fmaf(vx, vx, yy);
            }
    g_K[m * DP + 27] = 1.0f;     // ssum-in-accumulator trick
    g_Q[m * DP + 27] = 0.0f;     // keeps dot product exact
    g_yyc[m] = yy * YSC;
}

// ---------------------------------------------------------------------------
// Kernel B: flash attention, split-K, packed f32x2 math, threshold skip.
// score (log2 domain): sc = dot * (2*log2e/0.35) - yyc[m]
// Keys with sc < mmax - SKIP_THR contribute weight <= 2^-30 -> skipped
// (safe: mmax is monotone, so skipped weight can only shrink further).
// acc[27] accumulates the softmax mass (K pad element = 1).
// ---------------------------------------------------------------------------
__global__ __launch_bounds__(BQ, 2) void attn_kernel() {
    __shared__ __align__(16) float sK[BK * DP];
    __shared__ float sY[BK];

    int tid = threadIdx.x;
    int q = blockIdx.x * BQ + tid;
    int ql = q < LQ ? q : LQ - 1;
    int k0 = blockIdx.y * CH;
    int k1 = k0 + CH;

    const float S2 = 2.0f * 1.4426950408889634f / 0.35f;

    u64 qv[DP2];
#pragma unroll
    for (int p = 0; p < DP2 / 2; p++) {
        ulonglong2 t = ((const ulonglong2*)&g_Q[ql * DP])[p];
        qv[2 * p] = t.x; qv[2 * p + 1] = t.y;
    }
    u64 acc[DP2];
#pragma unroll
    for (int j = 0; j < DP2; j++) acc[j] = 0ull;
    float mmax = -CUDART_INF_F;

    for (int kt = k0; kt < k1; kt += BK) {
        int nk = min(BK, k1 - kt);          // CH is not a BK multiple
        for (int t = tid; t < nk * (DP / 4); t += BQ) {
            int kr = t / (DP / 4), p = t % (DP / 4);
            ((float4*)sK)[kr * (DP / 4) + p] =
                ((const float4*)g_K)[(kt + kr) * (DP / 4) + p];
        }
        for (int t = tid; t < nk; t += BQ) sY[t] = g_yyc[kt + t];
        __syncthreads();

        for (int kk = 0; kk < nk; kk++) {
            const char* krow = (const char*)&sK[kk * DP];
            u64 kv[DP2];
#pragma unroll
            for (int p = 0; p < DP2 / 2; p++)
                lds_v2u64(kv[2 * p], kv[2 * p + 1], krow + 16 * p);

            // packed dot product, 2 chains
            u64 d0 = fma2v(qv[0], kv[0], 0ull);
            u64 d1 = fma2v(qv[1], kv[1], 0ull);
#pragma unroll
            for (int j = 2; j < DP2; j += 2) {
                d0 = fma2v(qv[j], kv[j], d0);
                d1 = fma2v(qv[j + 1], kv[j + 1], d1);
            }
            d0 = add2v(d0, d1);
            float lo, hi;
            unpack2(d0, lo, hi);
            float sc = fmaf(lo + hi, S2, -sY[kk]);

            // warp-uniform skip: negligible keys never touch ex2 / acc
            if (__any_sync(0xffffffffu, sc > mmax - SKIP_THR)) {
                if (sc > mmax) {            // rare rescale (peaked softmax)
                    float corr = ex2(mmax - sc);
                    u64 c2 = pack2(corr, corr);
#pragma unroll
                    for (int j = 0; j < DP2; j++) acc[j] = mul2v(acc[j], c2);
                    mmax = sc;
                }
                float p = ex2(sc - mmax);
                u64 p2 = pack2(p, p);
#pragma unroll
                for (int j = 0; j < DP2; j++)
                    acc[j] = fma2v(p2, kv[j], acc[j]);
            }
        }
        __syncthreads();
    }

    if (q < LQ) {
        int sidx = blockIdx.y * LQ + q;
        g_pm[sidx] = mmax;
        ulonglong2* dst = (ulonglong2*)&g_pacc[(size_t)sidx * DP];
#pragma unroll
        for (int p = 0; p < DP2 / 2; p++) {
            ulonglong2 t;
            t.x = acc[2 * p]; t.y = acc[2 * p + 1];
            dst[p] = t;
        }
    }
}

// ---------------------------------------------------------------------------
// Kernel C: log-sum-exp merge of the SPLIT partials, normalize.
// o[27] = total softmax mass (from the K-pad trick)
// ---------------------------------------------------------------------------
__global__ void merge_kernel() {
    int q = blockIdx.x * blockDim.x + threadIdx.x;
    if (q >= LQ) return;
    float M = -CUDART_INF_F;
#pragma unroll
    for (int s = 0; s < SPLIT; s++) M = fmaxf(M, g_pm[s * LQ + q]);
    float o[DP];
#pragma unroll
    for (int j = 0; j < DP; j++) o[j] = 0.f;
#pragma unroll
    for (int s = 0; s < SPLIT; s++) {
        float w = ex2(g_pm[s * LQ + q] - M);
        const float4* src = (const float4*)&g_pacc[(size_t)(s * LQ + q) * DP];
#pragma unroll
        for (int p = 0; p < DP / 4; p++) {
            float4 t = src[p];
            o[4 * p]     = fmaf(t.x, w, o[4 * p]);
            o[4 * p + 1] = fmaf(t.y, w, o[4 * p + 1]);
            o[4 * p + 2] = fmaf(t.z, w, o[4 * p + 2]);
            o[4 * p + 3] = fmaf(t.w, w, o[4 * p + 3]);
        }
    }
    float inv = 1.0f / o[27];
#pragma unroll
    for (int p = 0; p < DP / 4; p++) {
        float4 t;
        t.x = o[4 * p] * inv; t.y = o[4 * p + 1] * inv;
        t.z = o[4 * p + 2] * inv; t.w = o[4 * p + 3] * inv;
        ((float4*)&g_outP[q * DP])[p] = t;
    }
}

// ---------------------------------------------------------------------------
// Kernel D: overlap-add fold with analytic contribution counts
// ---------------------------------------------------------------------------
__global__ void fold_kernel(float* __restrict__ out) {
    int idx = blockIdx.x * blockDim.x + threadIdx.x;
    if (idx >= 3 * 128 * 128) return;
    int c = idx / 16384;
    int h = (idx / 128) % 128;
    int w = idx % 128;
    int nh = min(h, 125) - max(0, h - 2) + 1;
    int nw = min(w, 125) - max(0, w - 2) + 1;
    float sum = 0.f;
#pragma unroll
    for (int ki = 0; ki < 3; ki++) {
        int ph = h - ki;
        if (ph < 0 || ph >= HO) continue;
#pragma unroll
        for (int kj = 0; kj < 3; kj++) {
            int pw = w - kj;
            if (pw < 0 || pw >= HO) continue;
            sum += g_outP[(ph * HO + pw) * DP + c * 9 + ki * 3 + kj];
        }
    }
    out[idx] = sum / (float)(nh * nw);
}

// ---------------------------------------------------------------------------
extern "C" void kernel_launch(void* const* d_in, const int* in_sizes, int n_in,
                              void* d_out, int out_size) {
    const float* x = (const float*)d_in[0];
    const float* y = (const float*)d_in[1];
    float* out = (float*)d_out;

    extract_kernel<<<(LQ + 255) / 256, 256>>>(x, y);
    dim3 grid(NQB, SPLIT);
    attn_kernel<<<grid, BQ>>>();
    merge_kernel<<<(LQ + 255) / 256, 256>>>();
    fold_kernel<<<(3 * 128 * 128 + 255) / 256, 256>>>(out);
}